// round 9
// baseline (speedup 1.0000x reference)
#include <cuda_runtime.h>
#include <cuda_fp16.h>
#include <cstdint>

#define M_DIM 1024
#define N_DIM 512
#define K_DIM 512

#define BM 64
#define BN 64
#define KC 64                 // fp16 per chunk -> 128B rows (SW128)
#define NCH (K_DIM / KC)      // 8
#define NTHREADS 512

// stage layout (bytes): Ahi 8K | Alo 8K | Bhi 8K = 24KB, double buffered
#define A_HI 0
#define A_LO 8192
#define B_HI 16384
#define STAGE 24576
#define SMEM_DYN (2 * STAGE)   // 48KB

// ---------------- helpers ----------------
__device__ __forceinline__ uint32_t smem_u32(const void* p) {
    uint32_t a;
    asm("{ .reg .u64 t; cvta.to.shared.u64 t, %1; cvt.u32.u64 %0, t; }"
        : "=r"(a) : "l"(p));
    return a;
}
__device__ __forceinline__ uint32_t sw128(uint32_t off) {
    return off ^ ((off >> 3) & 0x70);
}
__device__ __forceinline__ void ldsm4(uint32_t* r, uint32_t addr) {
    asm volatile("ldmatrix.sync.aligned.m8n8.x4.shared.b16 {%0,%1,%2,%3}, [%4];"
                 : "=r"(r[0]), "=r"(r[1]), "=r"(r[2]), "=r"(r[3]) : "r"(addr));
}
__device__ __forceinline__ void mma_f16(float* c, const uint32_t* a, const uint32_t* b) {
    asm volatile(
        "mma.sync.aligned.m16n8k16.row.col.f32.f16.f16.f32 "
        "{%0,%1,%2,%3}, {%4,%5,%6,%7}, {%8,%9}, {%0,%1,%2,%3};"
        : "+f"(c[0]), "+f"(c[1]), "+f"(c[2]), "+f"(c[3])
        : "r"(a[0]), "r"(a[1]), "r"(a[2]), "r"(a[3]), "r"(b[0]), "r"(b[1]));
}
__device__ __forceinline__ uint32_t pack_hi(float a, float b) {
    __half2 h = __halves2half2(__float2half_rn(a), __float2half_rn(b));
    return *reinterpret_cast<uint32_t*>(&h);
}
__device__ __forceinline__ uint32_t pack_lo(float a, float b) {
    __half ha = __float2half_rn(a);
    __half hb = __float2half_rn(b);
    __half2 h = __halves2half2(__float2half_rn(a - __half2float(ha)),
                               __float2half_rn(b - __half2float(hb)));
    return *reinterpret_cast<uint32_t*>(&h);
}

// ---------------- fused kernel ----------------
__global__ __launch_bounds__(NTHREADS, 1)
void filp_kernel(const float* __restrict__ X,
                 const float* __restrict__ W,
                 const float* __restrict__ bias,
                 float* __restrict__ out)
{
    extern __shared__ char smem[];
    const uint32_t sbase = smem_u32(smem);

    const int tid  = threadIdx.x;
    const int lane = tid & 31;
    const int wid  = tid >> 5;           // 0..15
    const int wm   = (wid & 3) * 16;     // warp M offset
    const int wn   = (wid >> 2) * 16;    // warp N offset

    const int m0 = blockIdx.y * BM;
    const int n0 = blockIdx.x * BN;

    float acc_hh[2][4], acc_lh[2][4];
    #pragma unroll
    for (int b = 0; b < 2; b++)
        #pragma unroll
        for (int q = 0; q < 4; q++) { acc_hh[b][q] = 0.0f; acc_lh[b][q] = 0.0f; }

    const int arow_l  = lane & 15;
    const int ahalf16 = ((lane >> 4) & 1) * 16;
    const int brow_l  = (lane & 7) + ((lane & 16) ? 8 : 0);
    const int bhalf16 = ((lane >> 3) & 1) * 16;

    uint32_t fa_hi[2][4], fa_lo[2][4], fb_hi[2][4];

    auto load_frags = [&](uint32_t stb, int s, int pb) {
        const uint32_t kb_a = (uint32_t)(s * 32 + ahalf16);
        const uint32_t kb_b = (uint32_t)(s * 32 + bhalf16);
        const uint32_t ra = (uint32_t)(wm + arow_l);
        const uint32_t ao = ra * 128 + (kb_a ^ ((ra & 7) << 4));
        ldsm4(fa_hi[pb], stb + A_HI + ao);
        ldsm4(fa_lo[pb], stb + A_LO + ao);
        const uint32_t rb = (uint32_t)(wn + brow_l);
        const uint32_t bo = rb * 128 + (kb_b ^ ((rb & 7) << 4));
        ldsm4(fb_hi[pb], stb + B_HI + bo);
    };

    // LDG one chunk's fp32 into registers (4 float4 per thread)
    auto ldg_chunk = [&](int c, float4* v) {
        const int kc = c * KC;
        #pragma unroll
        for (int i = 0; i < 4; i++) {
            int u = i * NTHREADS + tid;     // 0..2047
            int r  = (u >> 4) & 63;
            int cu = u & 15;
            if (u < 1024)
                v[i] = *reinterpret_cast<const float4*>(
                    X + (size_t)(m0 + r) * K_DIM + kc + cu * 4);
            else
                v[i] = *reinterpret_cast<const float4*>(
                    W + (size_t)(n0 + r) * K_DIM + kc + cu * 4);
        }
    };

    // convert + STS one chunk into stage st
    auto sts_chunk = [&](int st, const float4* v) {
        #pragma unroll
        for (int i = 0; i < 4; i++) {
            int u = i * NTHREADS + tid;
            int r  = (u >> 4) & 63;
            int cu = u & 15;                 // 8B unit within 128B row
            uint32_t off = sw128((uint32_t)(r * 128 + cu * 8));
            uint2 hi;
            hi.x = pack_hi(v[i].x, v[i].y);
            hi.y = pack_hi(v[i].z, v[i].w);
            if (u < 1024) {
                *reinterpret_cast<uint2*>(&smem[st * STAGE + A_HI + off]) = hi;
                uint2 lo;
                lo.x = pack_lo(v[i].x, v[i].y);
                lo.y = pack_lo(v[i].z, v[i].w);
                *reinterpret_cast<uint2*>(&smem[st * STAGE + A_LO + off]) = lo;
            } else {
                *reinterpret_cast<uint2*>(&smem[st * STAGE + B_HI + off]) = hi;
            }
        }
    };

    // ---- prologue ----
    float4 vreg[4];
    ldg_chunk(0, vreg);
    sts_chunk(0, vreg);
    if (NCH > 1) ldg_chunk(1, vreg);
    __syncthreads();

    for (int c = 0; c < NCH; c++) {
        // stage chunk c+1 into the other buffer; its previous readers (chunk
        // c-1) all passed the barrier at the end of the previous iteration.
        if (c + 1 < NCH) {
            sts_chunk((c + 1) & 1, vreg);
            if (c + 2 < NCH) ldg_chunk(c + 2, vreg);
        }

        const uint32_t stb = sbase + (c & 1) * STAGE;
        load_frags(stb, 0, 0);
        #pragma unroll
        for (int s = 0; s < 4; s++) {
            const int cur = s & 1;
            if (s < 3) load_frags(stb, s + 1, cur ^ 1);
            mma_f16(acc_hh[0], fa_hi[cur], &fb_hi[cur][0]);
            mma_f16(acc_hh[1], fa_hi[cur], &fb_hi[cur][2]);
            mma_f16(acc_lh[0], fa_lo[cur], &fb_hi[cur][0]);
            mma_f16(acc_lh[1], fa_lo[cur], &fb_hi[cur][2]);
        }
        __syncthreads();
    }

    // ---- fused epilogue: out = x * (hh + lh) + bias ----
    #pragma unroll
    for (int nt = 0; nt < 2; nt++) {
        const int m = m0 + wm + (lane >> 2);
        const int n = n0 + wn + nt * 8 + (lane & 3) * 2;
        float wx0 = acc_hh[nt][0] + acc_lh[nt][0];
        float wx1 = acc_hh[nt][1] + acc_lh[nt][1];
        float wx2 = acc_hh[nt][2] + acc_lh[nt][2];
        float wx3 = acc_hh[nt][3] + acc_lh[nt][3];
        const float2 bb = *reinterpret_cast<const float2*>(bias + n);
        const float2 x0 = *reinterpret_cast<const float2*>(X + (size_t)m * K_DIM + n);
        const float2 x1 = *reinterpret_cast<const float2*>(X + (size_t)(m + 8) * K_DIM + n);
        float2 o0, o1;
        o0.x = fmaf(x0.x, wx0, bb.x);
        o0.y = fmaf(x0.y, wx1, bb.y);
        o1.x = fmaf(x1.x, wx2, bb.x);
        o1.y = fmaf(x1.y, wx3, bb.y);
        *reinterpret_cast<float2*>(out + (size_t)m * N_DIM + n) = o0;
        *reinterpret_cast<float2*>(out + (size_t)(m + 8) * N_DIM + n) = o1;
    }
}

// ---------------- launch ----------------
extern "C" void kernel_launch(void* const* d_in, const int* in_sizes, int n_in,
                              void* d_out, int out_size) {
    const float* x    = (const float*)d_in[0];   // (1024, 512)
    const float* w    = (const float*)d_in[1];   // (512, 512)
    const float* bias = (const float*)d_in[2];   // (512,)
    float* out        = (float*)d_out;           // (1024, 512)

    cudaFuncSetAttribute(filp_kernel, cudaFuncAttributeMaxDynamicSharedMemorySize, SMEM_DYN);

    dim3 grid(N_DIM / BN, M_DIM / BM);   // (8, 16) = 128 CTAs
    filp_kernel<<<grid, NTHREADS, SMEM_DYN>>>(x, w, bias, out);
}

// round 10
// speedup vs baseline: 1.2083x; 1.2083x over previous
#include <cuda_runtime.h>
#include <cuda_fp16.h>
#include <cstdint>

#define M_DIM 1024
#define N_DIM 512
#define K_DIM 512

#define BM 64
#define BN 64
#define KC 64                 // fp16 per chunk -> 128B rows (SW128)
#define NCH (K_DIM / KC)      // 8
#define NTHREADS 512

// stage layout (bytes): A 8K | B 8K = 16KB, double buffered
#define A_OFF 0
#define B_OFF 8192
#define STAGE 16384
#define SMEM_DYN (2 * STAGE)   // 32KB

// ---------------- helpers ----------------
__device__ __forceinline__ uint32_t smem_u32(const void* p) {
    uint32_t a;
    asm("{ .reg .u64 t; cvta.to.shared.u64 t, %1; cvt.u32.u64 %0, t; }"
        : "=r"(a) : "l"(p));
    return a;
}
__device__ __forceinline__ uint32_t sw128(uint32_t off) {
    return off ^ ((off >> 3) & 0x70);
}
__device__ __forceinline__ void ldsm4(uint32_t* r, uint32_t addr) {
    asm volatile("ldmatrix.sync.aligned.m8n8.x4.shared.b16 {%0,%1,%2,%3}, [%4];"
                 : "=r"(r[0]), "=r"(r[1]), "=r"(r[2]), "=r"(r[3]) : "r"(addr));
}
__device__ __forceinline__ void mma_f16(float* c, const uint32_t* a, const uint32_t* b) {
    asm volatile(
        "mma.sync.aligned.m16n8k16.row.col.f32.f16.f16.f32 "
        "{%0,%1,%2,%3}, {%4,%5,%6,%7}, {%8,%9}, {%0,%1,%2,%3};"
        : "+f"(c[0]), "+f"(c[1]), "+f"(c[2]), "+f"(c[3])
        : "r"(a[0]), "r"(a[1]), "r"(a[2]), "r"(a[3]), "r"(b[0]), "r"(b[1]));
}
__device__ __forceinline__ uint32_t pack_hi(float a, float b) {
    __half2 h = __halves2half2(__float2half_rn(a), __float2half_rn(b));
    return *reinterpret_cast<uint32_t*>(&h);
}

// ---------------- fused kernel ----------------
__global__ __launch_bounds__(NTHREADS, 1)
void filp_kernel(const float* __restrict__ X,
                 const float* __restrict__ W,
                 const float* __restrict__ bias,
                 float* __restrict__ out)
{
    extern __shared__ char smem[];
    const uint32_t sbase = smem_u32(smem);

    const int tid  = threadIdx.x;
    const int lane = tid & 31;
    const int wid  = tid >> 5;           // 0..15
    const int wm   = (wid & 3) * 16;     // warp M offset
    const int wn   = (wid >> 2) * 16;    // warp N offset

    const int m0 = blockIdx.y * BM;
    const int n0 = blockIdx.x * BN;

    float acc[2][4];
    #pragma unroll
    for (int b = 0; b < 2; b++)
        #pragma unroll
        for (int q = 0; q < 4; q++) acc[b][q] = 0.0f;

    const int arow_l  = lane & 15;
    const int ahalf16 = ((lane >> 4) & 1) * 16;
    const int brow_l  = (lane & 7) + ((lane & 16) ? 8 : 0);
    const int bhalf16 = ((lane >> 3) & 1) * 16;

    uint32_t fa[2][4], fb[2][4];

    auto load_frags = [&](uint32_t stb, int s, int pb) {
        const uint32_t kb_a = (uint32_t)(s * 32 + ahalf16);
        const uint32_t kb_b = (uint32_t)(s * 32 + bhalf16);
        const uint32_t ra = (uint32_t)(wm + arow_l);
        const uint32_t ao = ra * 128 + (kb_a ^ ((ra & 7) << 4));
        ldsm4(fa[pb], stb + A_OFF + ao);
        const uint32_t rb = (uint32_t)(wn + brow_l);
        const uint32_t bo = rb * 128 + (kb_b ^ ((rb & 7) << 4));
        ldsm4(fb[pb], stb + B_OFF + bo);
    };

    // LDG one chunk's fp32 into registers (4 float4 per thread)
    auto ldg_chunk = [&](int c, float4* v) {
        const int kc = c * KC;
        #pragma unroll
        for (int i = 0; i < 4; i++) {
            int u = i * NTHREADS + tid;     // 0..2047
            int r  = (u >> 4) & 63;
            int cu = u & 15;
            if (u < 1024)
                v[i] = *reinterpret_cast<const float4*>(
                    X + (size_t)(m0 + r) * K_DIM + kc + cu * 4);
            else
                v[i] = *reinterpret_cast<const float4*>(
                    W + (size_t)(n0 + r) * K_DIM + kc + cu * 4);
        }
    };

    // convert + STS one chunk into stage st
    auto sts_chunk = [&](int st, const float4* v) {
        #pragma unroll
        for (int i = 0; i < 4; i++) {
            int u = i * NTHREADS + tid;
            int r  = (u >> 4) & 63;
            int cu = u & 15;                 // 8B unit within 128B row
            uint32_t off = sw128((uint32_t)(r * 128 + cu * 8));
            uint2 hi;
            hi.x = pack_hi(v[i].x, v[i].y);
            hi.y = pack_hi(v[i].z, v[i].w);
            if (u < 1024)
                *reinterpret_cast<uint2*>(&smem[st * STAGE + A_OFF + off]) = hi;
            else
                *reinterpret_cast<uint2*>(&smem[st * STAGE + B_OFF + off]) = hi;
        }
    };

    // ---- prologue ----
    float4 vreg[4];
    ldg_chunk(0, vreg);
    sts_chunk(0, vreg);
    if (NCH > 1) ldg_chunk(1, vreg);
    __syncthreads();

    for (int c = 0; c < NCH; c++) {
        // stage chunk c+1 into the other buffer; its previous readers (chunk
        // c-1) all passed the barrier at the end of the previous iteration.
        if (c + 1 < NCH) {
            sts_chunk((c + 1) & 1, vreg);
            if (c + 2 < NCH) ldg_chunk(c + 2, vreg);
        }

        const uint32_t stb = sbase + (c & 1) * STAGE;
        load_frags(stb, 0, 0);
        #pragma unroll
        for (int s = 0; s < 4; s++) {
            const int cur = s & 1;
            if (s < 3) load_frags(stb, s + 1, cur ^ 1);
            mma_f16(acc[0], fa[cur], &fb[cur][0]);
            mma_f16(acc[1], fa[cur], &fb[cur][2]);
        }
        __syncthreads();
    }

    // ---- fused epilogue: out = x * wx + bias ----
    #pragma unroll
    for (int nt = 0; nt < 2; nt++) {
        const int m = m0 + wm + (lane >> 2);
        const int n = n0 + wn + nt * 8 + (lane & 3) * 2;
        const float2 bb = *reinterpret_cast<const float2*>(bias + n);
        const float2 x0 = *reinterpret_cast<const float2*>(X + (size_t)m * K_DIM + n);
        const float2 x1 = *reinterpret_cast<const float2*>(X + (size_t)(m + 8) * K_DIM + n);
        float2 o0, o1;
        o0.x = fmaf(x0.x, acc[nt][0], bb.x);
        o0.y = fmaf(x0.y, acc[nt][1], bb.y);
        o1.x = fmaf(x1.x, acc[nt][2], bb.x);
        o1.y = fmaf(x1.y, acc[nt][3], bb.y);
        *reinterpret_cast<float2*>(out + (size_t)m * N_DIM + n) = o0;
        *reinterpret_cast<float2*>(out + (size_t)(m + 8) * N_DIM + n) = o1;
    }
}

// ---------------- launch ----------------
extern "C" void kernel_launch(void* const* d_in, const int* in_sizes, int n_in,
                              void* d_out, int out_size) {
    const float* x    = (const float*)d_in[0];   // (1024, 512)
    const float* w    = (const float*)d_in[1];   // (512, 512)
    const float* bias = (const float*)d_in[2];   // (512,)
    float* out        = (float*)d_out;           // (1024, 512)

    cudaFuncSetAttribute(filp_kernel, cudaFuncAttributeMaxDynamicSharedMemorySize, SMEM_DYN);

    dim3 grid(N_DIM / BN, M_DIM / BM);   // (8, 16) = 128 CTAs
    filp_kernel<<<grid, NTHREADS, SMEM_DYN>>>(x, w, bias, out);
}

// round 11
// speedup vs baseline: 1.2119x; 1.0030x over previous
#include <cuda_runtime.h>
#include <cuda_fp16.h>
#include <cstdint>

#define M_DIM 1024
#define N_DIM 512
#define K_DIM 512

#define BM 64
#define BN 64
#define KC 64                  // fp16 per chunk -> 128B SW128 rows
#define NCHUNK (K_DIM / KC)    // 8
#define NTHREADS 512

// per-chunk layout (verified): A 8KB | B 8KB = 16KB; 8 chunks consecutive
#define A_OFF 0
#define B_OFF 8192
#define CHUNK_BYTES 16384
#define SMEM_DYN (NCHUNK * CHUNK_BYTES)   // 128KB, whole K resident

// ---------------- helpers ----------------
__device__ __forceinline__ uint32_t smem_u32(const void* p) {
    uint32_t a;
    asm("{ .reg .u64 t; cvta.to.shared.u64 t, %1; cvt.u32.u64 %0, t; }"
        : "=r"(a) : "l"(p));
    return a;
}
__device__ __forceinline__ uint32_t sw128(uint32_t off) {
    return off ^ ((off >> 3) & 0x70);
}
__device__ __forceinline__ void ldsm4(uint32_t* r, uint32_t addr) {
    asm volatile("ldmatrix.sync.aligned.m8n8.x4.shared.b16 {%0,%1,%2,%3}, [%4];"
                 : "=r"(r[0]), "=r"(r[1]), "=r"(r[2]), "=r"(r[3]) : "r"(addr));
}
__device__ __forceinline__ void mma_f16(float* c, const uint32_t* a, const uint32_t* b) {
    asm volatile(
        "mma.sync.aligned.m16n8k16.row.col.f32.f16.f16.f32 "
        "{%0,%1,%2,%3}, {%4,%5,%6,%7}, {%8,%9}, {%0,%1,%2,%3};"
        : "+f"(c[0]), "+f"(c[1]), "+f"(c[2]), "+f"(c[3])
        : "r"(a[0]), "r"(a[1]), "r"(a[2]), "r"(a[3]), "r"(b[0]), "r"(b[1]));
}
__device__ __forceinline__ uint32_t pack_hi(float a, float b) {
    __half2 h = __halves2half2(__float2half_rn(a), __float2half_rn(b));
    return *reinterpret_cast<uint32_t*>(&h);
}

// ---------------- fused kernel ----------------
__global__ __launch_bounds__(NTHREADS, 1)
void filp_kernel(const float* __restrict__ X,
                 const float* __restrict__ W,
                 const float* __restrict__ bias,
                 float* __restrict__ out)
{
    extern __shared__ char smem[];
    const uint32_t sbase = smem_u32(smem);

    const int tid  = threadIdx.x;
    const int lane = tid & 31;
    const int wid  = tid >> 5;           // 0..15
    const int wm   = (wid & 3) * 16;     // warp M offset
    const int wn   = (wid >> 2) * 16;    // warp N offset

    const int m0 = blockIdx.y * BM;
    const int n0 = blockIdx.x * BN;

    float acc[2][4];
    #pragma unroll
    for (int b = 0; b < 2; b++)
        #pragma unroll
        for (int q = 0; q < 4; q++) acc[b][q] = 0.0f;

    const int arow_l  = lane & 15;
    const int ahalf16 = ((lane >> 4) & 1) * 16;
    const int brow_l  = (lane & 7) + ((lane & 16) ? 8 : 0);
    const int bhalf16 = ((lane >> 3) & 1) * 16;

    uint32_t fa[2][4], fb[2][4];

    // frag load for k-substep s (0..3) of chunk at stb
    auto load_frags = [&](uint32_t stb, int s, int pb) {
        const uint32_t kb_a = (uint32_t)(s * 32 + ahalf16);
        const uint32_t kb_b = (uint32_t)(s * 32 + bhalf16);
        const uint32_t ra = (uint32_t)(wm + arow_l);
        const uint32_t ao = ra * 128 + (kb_a ^ ((ra & 7) << 4));
        ldsm4(fa[pb], stb + A_OFF + ao);
        const uint32_t rb = (uint32_t)(wn + brow_l);
        const uint32_t bo = rb * 128 + (kb_b ^ ((rb & 7) << 4));
        ldsm4(fb[pb], stb + B_OFF + bo);
    };

    // LDG one chunk's fp32 (4 float4 per thread)
    auto ldg_chunk = [&](int c, float4* v) {
        const int kc = c * KC;
        #pragma unroll
        for (int i = 0; i < 4; i++) {
            int u = i * NTHREADS + tid;     // 0..2047
            int r  = (u >> 4) & 63;
            int cu = u & 15;
            if (u < 1024)
                v[i] = *reinterpret_cast<const float4*>(
                    X + (size_t)(m0 + r) * K_DIM + kc + cu * 4);
            else
                v[i] = *reinterpret_cast<const float4*>(
                    W + (size_t)(n0 + r) * K_DIM + kc + cu * 4);
        }
    };

    // convert + STS one chunk into its resident slot
    auto sts_chunk = [&](int c, const float4* v) {
        const int base = c * CHUNK_BYTES;
        #pragma unroll
        for (int i = 0; i < 4; i++) {
            int u = i * NTHREADS + tid;
            int r  = (u >> 4) & 63;
            int cu = u & 15;                 // 8B unit within 128B row
            uint32_t off = sw128((uint32_t)(r * 128 + cu * 8));
            uint2 hi;
            hi.x = pack_hi(v[i].x, v[i].y);
            hi.y = pack_hi(v[i].z, v[i].w);
            if (u < 1024)
                *reinterpret_cast<uint2*>(&smem[base + A_OFF + off]) = hi;
            else
                *reinterpret_cast<uint2*>(&smem[base + B_OFF + off]) = hi;
        }
    };

    // ---- load ENTIRE K into smem: LDG chunks back-to-back (high MLP),
    //      convert+STS as each arrives; no barriers in between ----
    float4 vreg[2][4];
    ldg_chunk(0, vreg[0]);
    #pragma unroll
    for (int c = 0; c < NCHUNK; c++) {
        if (c + 1 < NCHUNK) ldg_chunk(c + 1, vreg[(c + 1) & 1]);
        sts_chunk(c, vreg[c & 1]);
    }
    __syncthreads();   // the ONLY barrier

    // ---- 32 k-steps straight through, frag double-buffered ----
    load_frags(sbase, 0, 0);
    #pragma unroll
    for (int c = 0; c < NCHUNK; c++) {
        #pragma unroll
        for (int s = 0; s < 4; s++) {
            const int ks  = c * 4 + s;
            const int cur = ks & 1;
            if (ks < 31) {
                const int nk = ks + 1;
                load_frags(sbase + (uint32_t)(nk >> 2) * CHUNK_BYTES, nk & 3, cur ^ 1);
            }
            mma_f16(acc[0], fa[cur], &fb[cur][0]);
            mma_f16(acc[1], fa[cur], &fb[cur][2]);
        }
    }

    // ---- fused epilogue: out = x * wx + bias ----
    #pragma unroll
    for (int nt = 0; nt < 2; nt++) {
        const int m = m0 + wm + (lane >> 2);
        const int n = n0 + wn + nt * 8 + (lane & 3) * 2;
        const float2 bb = *reinterpret_cast<const float2*>(bias + n);
        const float2 x0 = *reinterpret_cast<const float2*>(X + (size_t)m * K_DIM + n);
        const float2 x1 = *reinterpret_cast<const float2*>(X + (size_t)(m + 8) * K_DIM + n);
        float2 o0, o1;
        o0.x = fmaf(x0.x, acc[nt][0], bb.x);
        o0.y = fmaf(x0.y, acc[nt][1], bb.y);
        o1.x = fmaf(x1.x, acc[nt][2], bb.x);
        o1.y = fmaf(x1.y, acc[nt][3], bb.y);
        *reinterpret_cast<float2*>(out + (size_t)m * N_DIM + n) = o0;
        *reinterpret_cast<float2*>(out + (size_t)(m + 8) * N_DIM + n) = o1;
    }
}

// ---------------- launch ----------------
extern "C" void kernel_launch(void* const* d_in, const int* in_sizes, int n_in,
                              void* d_out, int out_size) {
    const float* x    = (const float*)d_in[0];   // (1024, 512)
    const float* w    = (const float*)d_in[1];   // (512, 512)
    const float* bias = (const float*)d_in[2];   // (512,)
    float* out        = (float*)d_out;           // (1024, 512)

    cudaFuncSetAttribute(filp_kernel, cudaFuncAttributeMaxDynamicSharedMemorySize, SMEM_DYN);

    dim3 grid(N_DIM / BN, M_DIM / BM);   // (8, 16) = 128 CTAs
    filp_kernel<<<grid, NTHREADS, SMEM_DYN>>>(x, w, bias, out);
}